// round 14
// baseline (speedup 1.0000x reference)
#include <cuda_runtime.h>
#include <cuda_bf16.h>
#include <math.h>

// ---------------------------------------------------------------------------
// ESpaceLoss: biquad filter bank fwd+bwd -> tanh(W x) -> mean |p - t|
//
//   prep    : value-classified, dtype-robust coefficient load + analytic
//             fp64 reconstruction; W -> bf16; A = M^250 by binary powering.
//   pass1a  : per (seq,chunk) zero-init fp32 recurrence (plain fp32 coeffs,
//             4-cyc chain), END STATES ONLY -> g_E.  320 chunks of 250.
//   combine : hierarchical scan (8 seg x 40 chunks, A^40 jumps) -> exact
//             fp64 init states g_S for chunks 160..319.
//   pass1b  : re-run chunks 160..319 seeded with exact states (double-float
//             coefficients); writes final corrected bf16 Y directly.
//   stageB  : cp.async staging + bf16 mma.sync GEMM + tanh.approx |diff|.
//   finalize: deterministic reduction -> scalar mean
// ---------------------------------------------------------------------------

#define TLEN   120000
#define LCH    250
#define NCHUNK 320
#define CH0    160
#define NCHV   160
#define MARGIN 40000
#define TV     40000
#define NC     64
#define NSEQ   16
#define TT     64          // stage B t-tile
#define NTB    (TV / TT)   // 625
#define NPART  (NTB * 4)   // 2500

#define ROWB   272                     // bf16 tile row stride in bytes (17 lines)
#define WBYTES (64 * ROWB)             // 17408
#define VSIGB  (64 * ROWB)             // 17408 per signal
#define SMEM_B (WBYTES + 2 * VSIGB)    // 52224

__device__ double g_c[3][NC];                  // a1, a2, b0 (normalized fp64)
__device__ double g_A[NC][4];                  // chunk transition M^LCH
__device__ double g_E[NSEQ][NCHUNK][NC][2];    // particular end states
__device__ double g_S[NSEQ][NCHV][NC][2];      // exact init state (s1,s2)
__device__ unsigned g_Wh[4096];                // W as bf16x2, [o][c-pair]
__device__ __nv_bfloat16 g_Yh[(size_t)2 * 4 * TV * 128]; // [sig][b][t][dir*64+c]
__device__ double g_part[NPART];

// ---------------------------------------------------------------------------
// Coefficient prep + W pack + A = M^250.
// ---------------------------------------------------------------------------
__device__ __forceinline__ int coeff_class(double v) {
    if (!isfinite(v)) return -1;
    if (v > -2.5 && v < -1.5) return 0;       // a1
    if (v >  0.5 && v <  1.5) return 1;       // a2
    if (v > 1e-7 && v < 1e-2) return 2;       // b0
    return -1;
}

__global__ void __launch_bounds__(64) prep(const void* p0, const void* p1,
                                           const void* p2,
                                           const float* __restrict__ W) {
    const void* bufs[3] = { p0, p1, p2 };
    int c = threadIdx.x;
    __shared__ int slot[3];
    __shared__ int use64;
    __shared__ int mism;

    if (c == 0) {
        int cf[3], cd[3];
        for (int k = 0; k < 3; ++k) {
            cf[k] = coeff_class((double)((const float*)bufs[k])[0]);
            cd[k] = coeff_class(((const double*)bufs[k])[0]);
        }
        bool okf = cf[0] >= 0 && cf[1] >= 0 && cf[2] >= 0 &&
                   cf[0] != cf[1] && cf[0] != cf[2] && cf[1] != cf[2];
        bool okd = cd[0] >= 0 && cd[1] >= 0 && cd[2] >= 0 &&
                   cd[0] != cd[1] && cd[0] != cd[2] && cd[1] != cd[2];
        use64 = okf ? 0 : 1;
        for (int k = 0; k < 3; ++k)
            slot[k] = okf ? cf[k] : (okd ? cd[k] : k);
        mism = 0;
    }
    __syncthreads();

    for (int k = 0; k < 3; ++k) {
        double v = use64 ? ((const double*)bufs[k])[c]
                         : (double)((const float*)bufs[k])[c];
        g_c[slot[k]][c] = v;
    }
    __syncthreads();

    const double PI = 3.14159265358979323846;
    double lmin = log(2.0 * PI * 10.0  / 24000.0);
    double lmax = log(2.0 * PI * 100.0 / 24000.0);
    double th = exp(lmin + (double)c * ((lmax - lmin) / 63.0));
    double r  = 0.9999 + (double)c * ((0.99999 - 0.9999) / 63.0);
    if (c == 63) { th = 2.0 * PI * 100.0 / 24000.0; r = 0.99999; }
    double ra1 = -2.0 * r * cos(th);
    double ra2 = r * r;
    double rb0 = (1.0 - r) * 0.5;

    if (fabs(ra1 - g_c[0][c]) > 1e-5 ||
        fabs(ra2 - g_c[1][c]) > 1e-5 ||
        fabs(rb0 - g_c[2][c]) > 1e-8)
        atomicOr(&mism, 1);
    __syncthreads();

    if (!mism) {
        g_c[0][c] = ra1;
        g_c[1][c] = ra2;
        g_c[2][c] = rb0;
    }
    __syncthreads();

    // A = M^LCH, M = [[-a1,-a2],[1,0]], by binary powering (fp64)
    {
        double m00 = -g_c[0][c], m01 = -g_c[1][c];
        double p00 = 1, p01 = 0, p10 = 0, p11 = 1;
        double b00 = m00, b01 = m01, b10 = 1.0, b11 = 0.0;
        int e = LCH;
        while (e) {
            if (e & 1) {
                double t00 = p00 * b00 + p01 * b10, t01 = p00 * b01 + p01 * b11;
                double t10 = p10 * b00 + p11 * b10, t11 = p10 * b01 + p11 * b11;
                p00 = t00; p01 = t01; p10 = t10; p11 = t11;
            }
            e >>= 1;
            if (e) {
                double t00 = b00 * b00 + b01 * b10, t01 = b00 * b01 + b01 * b11;
                double t10 = b10 * b00 + b11 * b10, t11 = b10 * b01 + b11 * b11;
                b00 = t00; b01 = t01; b10 = t10; b11 = t11;
            }
        }
        g_A[c][0] = p00; g_A[c][1] = p01;
        g_A[c][2] = p10; g_A[c][3] = p11;
    }

    // pack W -> bf16x2
    const float2* Wf2 = (const float2*)W;
    for (int i = c; i < 4096; i += 64) {
        float2 wv = Wf2[i];
        unsigned u;
        asm("cvt.rn.bf16x2.f32 %0, %1, %2;" : "=r"(u) : "f"(wv.y), "f"(wv.x));
        g_Wh[i] = u;
    }
}

// ---------------------------------------------------------------------------
// pass1a: zero-init recurrence, end states only. Warp = one (seq,chunk),
// 2 channels/thread, plain fp32 coefficients (4-cyc chain).
// ---------------------------------------------------------------------------
__global__ void __launch_bounds__(128) pass1a(
    const float* __restrict__ pred, const float* __restrict__ targ)
{
    __shared__ float xs4[4][LCH];
    int tid = threadIdx.x;
    int w = tid >> 5, l = tid & 31;
    int task = blockIdx.x * 4 + w;           // 0..5119
    int k = task % NCHUNK;
    int s = task / NCHUNK;
    int sig = s >> 3, b = (s >> 1) & 3, dir = s & 1;
    const float* x = (sig ? targ : pred) + b * TLEN;
    float* xs = xs4[w];

    int k0 = k * LCH;
    if (dir == 0) {
        for (int j = l; j < LCH; j += 32) xs[j] = x[k0 + j];
    } else {
        for (int j = l; j < LCH; j += 32) xs[j] = x[TLEN - 1 - (k0 + j)];
    }
    __syncwarp();

    int c0 = 2 * l, c1 = 2 * l + 1;
    float n1A = (float)(-g_c[0][c0]), n2A = (float)(-g_c[1][c0]);
    float n1B = (float)(-g_c[0][c1]), n2B = (float)(-g_c[1][c1]);
    float b0A = (float)g_c[2][c0], b0B = (float)g_c[2][c1];

    float y1a = 0.f, y2a = 0.f, y1b = 0.f, y2b = 0.f;
    #pragma unroll 5
    for (int j = 0; j < LCH; ++j) {
        float xj = xs[j];
        float ya = fmaf(n1A, y1a, fmaf(n2A, y2a, b0A * xj));
        float yb = fmaf(n1B, y1b, fmaf(n2B, y2b, b0B * xj));
        y2a = y1a; y1a = ya;
        y2b = y1b; y1b = yb;
    }
    g_E[s][k][c0][0] = (double)y1a;
    g_E[s][k][c0][1] = (double)y2a;
    g_E[s][k][c1][0] = (double)y1b;
    g_E[s][k][c1][1] = (double)y2b;
}

// ---------------------------------------------------------------------------
// combine: hierarchical scan. 512 thr = (c 0..63, seg 0..7); seg covers 40
// chunks (in-loop g_E loads). Phase2: 8-step boundary scan with A^40.
// Phase3: rescan segments 4..7 from exact boundary states -> g_S.
// ---------------------------------------------------------------------------
__global__ void __launch_bounds__(512) combine() {
    __shared__ double Lseg[8][NC][2];
    __shared__ double Sseg[8][NC][2];
    int s   = blockIdx.x;
    int c   = threadIdx.x & 63;
    int seg = threadIdx.x >> 6;

    double A00 = g_A[c][0], A01 = g_A[c][1], A10 = g_A[c][2], A11 = g_A[c][3];

    // phase 1: local scan from zero over this segment's 40 chunks
    double l1 = 0.0, l2 = 0.0;
    #pragma unroll 4
    for (int i = 0; i < 40; ++i) {
        double e1 = g_E[s][seg * 40 + i][c][0];
        double e2 = g_E[s][seg * 40 + i][c][1];
        double n1 = fma(A00, l1, fma(A01, l2, e1));
        double n2 = fma(A10, l1, fma(A11, l2, e2));
        l1 = n1; l2 = n2;
    }
    Lseg[seg][c][0] = l1;
    Lseg[seg][c][1] = l2;
    __syncthreads();

    // phase 2: boundary scan (seg==0 threads) with T = A^40
    if (seg == 0) {
        double B00 = fma(A00, A00, A01 * A10), B01 = fma(A00, A01, A01 * A11);
        double B10 = fma(A10, A00, A11 * A10), B11 = fma(A10, A01, A11 * A11);
        double C00 = fma(B00, B00, B01 * B10), C01 = fma(B00, B01, B01 * B11);
        double C10 = fma(B10, B00, B11 * B10), C11 = fma(B10, B01, B11 * B11);
        double D00 = fma(C00, C00, C01 * C10), D01 = fma(C00, C01, C01 * C11);  // A^8
        double D10 = fma(C10, C00, C11 * C10), D11 = fma(C10, C01, C11 * C11);
        double E00 = fma(D00, D00, D01 * D10), E01 = fma(D00, D01, D01 * D11);  // A^16
        double E10 = fma(D10, D00, D11 * D10), E11 = fma(D10, D01, D11 * D11);
        double F00 = fma(E00, E00, E01 * E10), F01 = fma(E00, E01, E01 * E11);  // A^32
        double F10 = fma(E10, E00, E11 * E10), F11 = fma(E10, E01, E11 * E11);
        double T00 = fma(F00, D00, F01 * D10), T01 = fma(F00, D01, F01 * D11);  // A^40
        double T10 = fma(F10, D00, F11 * D10), T11 = fma(F10, D01, F11 * D11);
        double s1 = 0.0, s2 = 0.0;
        #pragma unroll
        for (int g = 0; g < 8; ++g) {
            Sseg[g][c][0] = s1;
            Sseg[g][c][1] = s2;
            double e1 = Lseg[g][c][0], e2 = Lseg[g][c][1];
            double n1 = fma(T00, s1, fma(T01, s2, e1));
            double n2 = fma(T10, s1, fma(T11, s2, e2));
            s1 = n1; s2 = n2;
        }
    }
    __syncthreads();

    // phase 3: rescan from exact boundary state, emit states for k >= 160
    if (seg >= 4) {
        double s1 = Sseg[seg][c][0], s2 = Sseg[seg][c][1];
        #pragma unroll 4
        for (int i = 0; i < 40; ++i) {
            int k = seg * 40 + i;
            g_S[s][k - CH0][c][0] = s1;
            g_S[s][k - CH0][c][1] = s2;
            double e1 = g_E[s][k][c][0];
            double e2 = g_E[s][k][c][1];
            double n1 = fma(A00, s1, fma(A01, s2, e1));
            double n2 = fma(A10, s1, fma(A11, s2, e2));
            s1 = n1; s2 = n2;
        }
    }
}

// ---------------------------------------------------------------------------
// pass1b: chunks 160..319 with exact init states -> final bf16 Y.
// Double-float coefficients (output path).
// ---------------------------------------------------------------------------
__global__ void __launch_bounds__(128) pass1b(
    const float* __restrict__ pred, const float* __restrict__ targ)
{
    __shared__ float xs4[4][LCH];
    int tid = threadIdx.x;
    int w = tid >> 5, l = tid & 31;
    int task = blockIdx.x * 4 + w;           // 0..2559
    int kk = task % NCHV;
    int s  = task / NCHV;
    int k  = kk + CH0;
    int sig = s >> 3, b = (s >> 1) & 3, dir = s & 1;
    const float* x = (sig ? targ : pred) + b * TLEN;
    float* xs = xs4[w];

    int k0 = k * LCH;
    if (dir == 0) {
        for (int j = l; j < LCH; j += 32) xs[j] = x[k0 + j];
    } else {
        for (int j = l; j < LCH; j += 32) xs[j] = x[TLEN - 1 - (k0 + j)];
    }
    __syncwarp();

    int c0 = 2 * l, c1 = 2 * l + 1;
    double a1A = -g_c[0][c0], a2A = -g_c[1][c0];
    double a1B = -g_c[0][c1], a2B = -g_c[1][c1];
    float n1Ah = (float)a1A, n1Al = (float)(a1A - (double)n1Ah);
    float n2Ah = (float)a2A, n2Al = (float)(a2A - (double)n2Ah);
    float n1Bh = (float)a1B, n1Bl = (float)(a1B - (double)n1Bh);
    float n2Bh = (float)a2B, n2Bl = (float)(a2B - (double)n2Bh);
    float b0A = (float)g_c[2][c0], b0B = (float)g_c[2][c1];

    float y1a = (float)g_S[s][kk][c0][0], y2a = (float)g_S[s][kk][c0][1];
    float y1b = (float)g_S[s][kk][c1][0], y2b = (float)g_S[s][kk][c1][1];

    unsigned* yrow = (unsigned*)(g_Yh
        + (size_t)((sig * 4 + b) * TV) * 128 + dir * 64 + c0);
    int tl0 = dir ? (TLEN - 1 - MARGIN - k0) : (k0 - MARGIN);
    int tstep = dir ? -1 : 1;

    #pragma unroll 5
    for (int j = 0; j < LCH; ++j) {
        float xj = xs[j];
        float ia = fmaf(n2Al, y2a, b0A * xj);
        float ta = fmaf(n1Al, y1a, ia);
        float ma = fmaf(n2Ah, y2a, ta);
        float ya = fmaf(n1Ah, y1a, ma);
        float ib = fmaf(n2Bl, y2b, b0B * xj);
        float tb = fmaf(n1Bl, y1b, ib);
        float mb = fmaf(n2Bh, y2b, tb);
        float yb = fmaf(n1Bh, y1b, mb);
        unsigned o;
        asm("cvt.rn.bf16x2.f32 %0, %1, %2;" : "=r"(o) : "f"(yb), "f"(ya));
        yrow[(size_t)(tl0 + j * tstep) * 64] = o;
        y2a = y1a; y1a = ya;
        y2b = y1b; y1b = yb;
    }
}

// ---------------------------------------------------------------------------
// Stage B helpers
// ---------------------------------------------------------------------------
__device__ __forceinline__ float tanh_fast(float x) {
    float r;
    asm("tanh.approx.f32 %0, %1;" : "=f"(r) : "f"(x));
    return r;
}
__device__ __forceinline__ void ldsm4(unsigned& r0, unsigned& r1,
                                      unsigned& r2, unsigned& r3,
                                      unsigned addr) {
    asm volatile("ldmatrix.sync.aligned.m8n8.x4.shared.b16 {%0,%1,%2,%3}, [%4];"
                 : "=r"(r0), "=r"(r1), "=r"(r2), "=r"(r3) : "r"(addr));
}
__device__ __forceinline__ void mma16816(float* d, const unsigned* a,
                                         unsigned b0, unsigned b1) {
    asm volatile(
        "mma.sync.aligned.m16n8k16.row.col.f32.bf16.bf16.f32 "
        "{%0,%1,%2,%3}, {%4,%5,%6,%7}, {%8,%9}, {%0,%1,%2,%3};"
        : "+f"(d[0]), "+f"(d[1]), "+f"(d[2]), "+f"(d[3])
        : "r"(a[0]), "r"(a[1]), "r"(a[2]), "r"(a[3]), "r"(b0), "r"(b1));
}
__device__ __forceinline__ void cp16(unsigned dst, const void* src) {
    asm volatile("cp.async.ca.shared.global [%0], [%1], 16;"
                 :: "r"(dst), "l"(src));
}

// ---------------------------------------------------------------------------
// Stage B: staging + GEMM + epilogue (Y is already fully corrected).
// ---------------------------------------------------------------------------
__global__ void __launch_bounds__(128, 4) stageB() {
    extern __shared__ char sm[];
    int tid = threadIdx.x;
    int b   = blockIdx.y;
    int t0  = blockIdx.x * TT;
    unsigned sb = (unsigned)__cvta_generic_to_shared(sm);

    // ---- stage W (prepacked bf16) via cp.async: 1024 uint4 ----
    {
        const uint4* src = (const uint4*)g_Wh;
        #pragma unroll
        for (int it = 0; it < 8; ++it) {
            int i = tid + it * 128;
            int o = i >> 4, q = i & 15;
            cp16(sb + o * ROWB + q * 16, src + i);
        }
    }
    // ---- stage Y tiles via cp.async: 2048 uint4 (32KB) ----
    {
        const uint4* srcP = (const uint4*)(g_Yh + ((size_t)(0 * 4 + b) * TV + t0) * 128);
        const uint4* srcT = (const uint4*)(g_Yh + ((size_t)(1 * 4 + b) * TV + t0) * 128);
        #pragma unroll
        for (int it = 0; it < 16; ++it) {
            int idx = tid + it * 128;
            int R = idx >> 4, col = idx & 15;
            int sig = R >> 6, tt = R & 63;
            const uint4* src = (sig ? srcT : srcP) + tt * 16 + col;
            cp16(sb + WBYTES + sig * VSIGB + tt * ROWB + col * 16, src);
        }
    }
    asm volatile("cp.async.commit_group;" ::: "memory");
    asm volatile("cp.async.wait_group 0;" ::: "memory");
    __syncthreads();

    // ---- tensor-core GEMM ----
    int w = tid >> 5, lane = tid & 31;
    int tw = w * 16;
    unsigned a_base = sb + (unsigned)(lane & 15) * ROWB
                         + ((lane & 16) ? 16u : 0u);
    unsigned b_base = sb + WBYTES
                    + (unsigned)(tw + (lane & 7) + ((lane & 16) ? 8 : 0)) * ROWB
                    + ((lane & 8) ? 16u : 0u);

    float acc[2][4][2][4];
    #pragma unroll
    for (int s2 = 0; s2 < 2; ++s2)
        #pragma unroll
        for (int m = 0; m < 4; ++m)
            #pragma unroll
            for (int n = 0; n < 2; ++n)
                #pragma unroll
                for (int i = 0; i < 4; ++i) acc[s2][m][n][i] = 0.f;

    #pragma unroll
    for (int k = 0; k < 8; ++k) {
        unsigned a[4][4];
        #pragma unroll
        for (int m = 0; m < 4; ++m)
            ldsm4(a[m][0], a[m][1], a[m][2], a[m][3],
                  a_base + (unsigned)m * (16 * ROWB) + (unsigned)k * 32);
        #pragma unroll
        for (int s2 = 0; s2 < 2; ++s2) {
            unsigned r0, r1, r2, r3;
            ldsm4(r0, r1, r2, r3,
                  b_base + (unsigned)s2 * VSIGB + (unsigned)k * 32);
            #pragma unroll
            for (int m = 0; m < 4; ++m) {
                mma16816(acc[s2][m][0], a[m], r0, r1);
                mma16816(acc[s2][m][1], a[m], r2, r3);
            }
        }
    }

    // ---- epilogue: |tanh(p) - tanh(t)| ----
    float lsum = 0.f;
    #pragma unroll
    for (int m = 0; m < 4; ++m)
        #pragma unroll
        for (int n = 0; n < 2; ++n)
            #pragma unroll
            for (int i = 0; i < 4; ++i)
                lsum += fabsf(tanh_fast(acc[0][m][n][i])
                            - tanh_fast(acc[1][m][n][i]));

    #pragma unroll
    for (int off = 16; off; off >>= 1)
        lsum += __shfl_xor_sync(0xffffffffu, lsum, off);

    __shared__ float red[4];
    if (lane == 0) red[w] = lsum;
    __syncthreads();
    if (tid == 0)
        g_part[b * NTB + blockIdx.x] =
            (double)((red[0] + red[1]) + (red[2] + red[3]));
}

// ---------------------------------------------------------------------------
// Deterministic final reduction -> mean
// ---------------------------------------------------------------------------
__global__ void __launch_bounds__(256) finalize(float* out) {
    __shared__ double sd[256];
    double acc = 0.0;
    for (int i = threadIdx.x; i < NPART; i += 256) acc += g_part[i];
    sd[threadIdx.x] = acc;
    __syncthreads();
    for (int s = 128; s > 0; s >>= 1) {
        if (threadIdx.x < s) sd[threadIdx.x] += sd[threadIdx.x + s];
        __syncthreads();
    }
    if (threadIdx.x == 0)
        out[0] = (float)(sd[0] / (4.0 * 64.0 * 40000.0));
}

// ---------------------------------------------------------------------------
extern "C" void kernel_launch(void* const* d_in, const int* in_sizes, int n_in,
                              void* d_out, int out_size) {
    const float *pred = 0, *targ = 0, *W = 0;
    const void  *cf[3] = { 0, 0, 0 };
    int nBig = 0, nSmall = 0;
    for (int i = 0; i < n_in; ++i) {
        int sz = in_sizes[i];
        if (sz == 480000) {
            if (nBig == 0) pred = (const float*)d_in[i];
            else           targ = (const float*)d_in[i];
            ++nBig;
        } else if (sz == 64 && nSmall < 3) {
            cf[nSmall++] = d_in[i];
        } else if (sz == 8192) {
            W = (const float*)d_in[i];
        }
    }
    float* out = (float*)d_out;

    cudaFuncSetAttribute(stageB, cudaFuncAttributeMaxDynamicSharedMemorySize,
                         SMEM_B);

    prep<<<1, 64>>>(cf[0], cf[1], cf[2], W);
    pass1a<<<(NCHUNK * NSEQ) / 4, 128>>>(pred, targ);
    combine<<<NSEQ, 512>>>();
    pass1b<<<(NCHV * NSEQ) / 4, 128>>>(pred, targ);
    stageB<<<dim3(NTB, 4), 128, SMEM_B>>>();
    finalize<<<1, 256>>>(out);
}

// round 16
// speedup vs baseline: 1.7048x; 1.7048x over previous
#include <cuda_runtime.h>
#include <cuda_bf16.h>
#include <math.h>

// ---------------------------------------------------------------------------
// ESpaceLoss: biquad filter bank fwd+bwd -> tanh(W x) -> mean |p - t|
//
//   prep    : value-classified, dtype-robust coefficient load + analytic
//             fp64 reconstruction; W -> bf16; A = M^1000 by binary powering.
//   pass1a  : per (seq,chunk) zero-init fp32 recurrence, 1 channel/thread
//             (task = 64 thr), END STATES ONLY -> g_E.  80 chunks of 1000.
//   combine : hierarchical scan (8 seg x 10 chunks, A^10 jumps) -> exact
//             fp64 init states g_S for chunks 40..79.
//   pass1b  : re-run chunks 40..79 seeded with exact states (double-float
//             coefficients), 1 channel/thread; writes final bf16 Y.
//   stageB  : cp.async staging + bf16 mma.sync GEMM + tanh.approx |diff|.
//   finalize: deterministic reduction -> scalar mean
// ---------------------------------------------------------------------------

#define TLEN   120000
#define LCH    1000
#define NCHUNK 80
#define CH0    40
#define NCHV   40
#define MARGIN 40000
#define TV     40000
#define NC     64
#define NSEQ   16
#define TT     64          // stage B t-tile
#define NTB    (TV / TT)   // 625
#define NPART  (NTB * 4)   // 2500

#define ROWB   272                     // bf16 tile row stride in bytes (17 lines)
#define WBYTES (64 * ROWB)             // 17408
#define VSIGB  (64 * ROWB)             // 17408 per signal
#define SMEM_B (WBYTES + 2 * VSIGB)    // 52224

__device__ double g_c[3][NC];                  // a1, a2, b0 (normalized fp64)
__device__ double g_A[NC][4];                  // chunk transition M^LCH
__device__ double g_E[NSEQ][NCHUNK][NC][2];    // particular end states
__device__ double g_S[NSEQ][NCHV][NC][2];      // exact init state (s1,s2)
__device__ unsigned g_Wh[4096];                // W as bf16x2, [o][c-pair]
__device__ __nv_bfloat16 g_Yh[(size_t)2 * 4 * TV * 128]; // [sig][b][t][dir*64+c]
__device__ double g_part[NPART];

// ---------------------------------------------------------------------------
// Coefficient prep + W pack + A = M^1000.
// ---------------------------------------------------------------------------
__device__ __forceinline__ int coeff_class(double v) {
    if (!isfinite(v)) return -1;
    if (v > -2.5 && v < -1.5) return 0;       // a1
    if (v >  0.5 && v <  1.5) return 1;       // a2
    if (v > 1e-7 && v < 1e-2) return 2;       // b0
    return -1;
}

__global__ void __launch_bounds__(64) prep(const void* p0, const void* p1,
                                           const void* p2,
                                           const float* __restrict__ W) {
    const void* bufs[3] = { p0, p1, p2 };
    int c = threadIdx.x;
    __shared__ int slot[3];
    __shared__ int use64;
    __shared__ int mism;

    if (c == 0) {
        int cf[3], cd[3];
        for (int k = 0; k < 3; ++k) {
            cf[k] = coeff_class((double)((const float*)bufs[k])[0]);
            cd[k] = coeff_class(((const double*)bufs[k])[0]);
        }
        bool okf = cf[0] >= 0 && cf[1] >= 0 && cf[2] >= 0 &&
                   cf[0] != cf[1] && cf[0] != cf[2] && cf[1] != cf[2];
        bool okd = cd[0] >= 0 && cd[1] >= 0 && cd[2] >= 0 &&
                   cd[0] != cd[1] && cd[0] != cd[2] && cd[1] != cd[2];
        use64 = okf ? 0 : 1;
        for (int k = 0; k < 3; ++k)
            slot[k] = okf ? cf[k] : (okd ? cd[k] : k);
        mism = 0;
    }
    __syncthreads();

    for (int k = 0; k < 3; ++k) {
        double v = use64 ? ((const double*)bufs[k])[c]
                         : (double)((const float*)bufs[k])[c];
        g_c[slot[k]][c] = v;
    }
    __syncthreads();

    const double PI = 3.14159265358979323846;
    double lmin = log(2.0 * PI * 10.0  / 24000.0);
    double lmax = log(2.0 * PI * 100.0 / 24000.0);
    double th = exp(lmin + (double)c * ((lmax - lmin) / 63.0));
    double r  = 0.9999 + (double)c * ((0.99999 - 0.9999) / 63.0);
    if (c == 63) { th = 2.0 * PI * 100.0 / 24000.0; r = 0.99999; }
    double ra1 = -2.0 * r * cos(th);
    double ra2 = r * r;
    double rb0 = (1.0 - r) * 0.5;

    if (fabs(ra1 - g_c[0][c]) > 1e-5 ||
        fabs(ra2 - g_c[1][c]) > 1e-5 ||
        fabs(rb0 - g_c[2][c]) > 1e-8)
        atomicOr(&mism, 1);
    __syncthreads();

    if (!mism) {
        g_c[0][c] = ra1;
        g_c[1][c] = ra2;
        g_c[2][c] = rb0;
    }
    __syncthreads();

    // A = M^LCH, M = [[-a1,-a2],[1,0]], by binary powering (fp64)
    {
        double m00 = -g_c[0][c], m01 = -g_c[1][c];
        double p00 = 1, p01 = 0, p10 = 0, p11 = 1;
        double b00 = m00, b01 = m01, b10 = 1.0, b11 = 0.0;
        int e = LCH;
        while (e) {
            if (e & 1) {
                double t00 = p00 * b00 + p01 * b10, t01 = p00 * b01 + p01 * b11;
                double t10 = p10 * b00 + p11 * b10, t11 = p10 * b01 + p11 * b11;
                p00 = t00; p01 = t01; p10 = t10; p11 = t11;
            }
            e >>= 1;
            if (e) {
                double t00 = b00 * b00 + b01 * b10, t01 = b00 * b01 + b01 * b11;
                double t10 = b10 * b00 + b11 * b10, t11 = b10 * b01 + b11 * b11;
                b00 = t00; b01 = t01; b10 = t10; b11 = t11;
            }
        }
        g_A[c][0] = p00; g_A[c][1] = p01;
        g_A[c][2] = p10; g_A[c][3] = p11;
    }

    // pack W -> bf16x2
    const float2* Wf2 = (const float2*)W;
    for (int i = c; i < 4096; i += 64) {
        float2 wv = Wf2[i];
        unsigned u;
        asm("cvt.rn.bf16x2.f32 %0, %1, %2;" : "=r"(u) : "f"(wv.y), "f"(wv.x));
        g_Wh[i] = u;
    }
}

// ---------------------------------------------------------------------------
// pass1a: zero-init recurrence, end states only. Task = 64 threads (2 warps),
// 1 channel/thread, plain fp32 coefficients. Block = 128 thr = 2 tasks.
// ---------------------------------------------------------------------------
__global__ void __launch_bounds__(128) pass1a(
    const float* __restrict__ pred, const float* __restrict__ targ)
{
    __shared__ float xs2[2][LCH];
    int tid = threadIdx.x;
    int half = tid >> 6;                     // task within block
    int c    = tid & 63;                     // channel
    int task = blockIdx.x * 2 + half;        // 0..1279
    int k = task % NCHUNK;
    int s = task / NCHUNK;
    int sig = s >> 3, b = (s >> 1) & 3, dir = s & 1;
    const float* x = (sig ? targ : pred) + b * TLEN;
    float* xs = xs2[half];

    int k0 = k * LCH;
    if (dir == 0) {
        for (int j = c; j < LCH; j += 64) xs[j] = x[k0 + j];
    } else {
        for (int j = c; j < LCH; j += 64) xs[j] = x[TLEN - 1 - (k0 + j)];
    }
    __syncthreads();

    float n1 = (float)(-g_c[0][c]), n2 = (float)(-g_c[1][c]);
    float b0 = (float)g_c[2][c];

    float y1 = 0.f, y2 = 0.f;
    #pragma unroll 8
    for (int j = 0; j < LCH; ++j) {
        float y = fmaf(n1, y1, fmaf(n2, y2, b0 * xs[j]));
        y2 = y1; y1 = y;
    }
    g_E[s][k][c][0] = (double)y1;
    g_E[s][k][c][1] = (double)y2;
}

// ---------------------------------------------------------------------------
// combine: hierarchical scan. 512 thr = (c 0..63, seg 0..7); seg covers 10
// chunks. Phase1: local zero-init scans. Phase2: 8-step boundary scan with
// A^10 (seg==0 threads). Phase3: rescan segments 4..7 from exact boundary
// states, writing g_S for chunks 40..79.
// ---------------------------------------------------------------------------
__global__ void __launch_bounds__(512) combine() {
    __shared__ double Lseg[8][NC][2];
    __shared__ double Sseg[8][NC][2];
    int s   = blockIdx.x;
    int c   = threadIdx.x & 63;
    int seg = threadIdx.x >> 6;

    double A00 = g_A[c][0], A01 = g_A[c][1], A10 = g_A[c][2], A11 = g_A[c][3];

    // prefetch this segment's 10 end-state pairs (MLP=20)
    double e[10][2];
    #pragma unroll
    for (int i = 0; i < 10; ++i) {
        e[i][0] = g_E[s][seg * 10 + i][c][0];
        e[i][1] = g_E[s][seg * 10 + i][c][1];
    }

    // phase 1: local scan from zero
    double l1 = 0.0, l2 = 0.0;
    #pragma unroll
    for (int i = 0; i < 10; ++i) {
        double n1 = fma(A00, l1, fma(A01, l2, e[i][0]));
        double n2 = fma(A10, l1, fma(A11, l2, e[i][1]));
        l1 = n1; l2 = n2;
    }
    Lseg[seg][c][0] = l1;
    Lseg[seg][c][1] = l2;
    __syncthreads();

    // phase 2: boundary scan (seg==0 threads), T = A^10
    if (seg == 0) {
        double B00 = fma(A00, A00, A01 * A10), B01 = fma(A00, A01, A01 * A11);
        double B10 = fma(A10, A00, A11 * A10), B11 = fma(A10, A01, A11 * A11);
        double C00 = fma(B00, B00, B01 * B10), C01 = fma(B00, B01, B01 * B11);
        double C10 = fma(B10, B00, B11 * B10), C11 = fma(B10, B01, B11 * B11);
        double D00 = fma(C00, C00, C01 * C10), D01 = fma(C00, C01, C01 * C11);
        double D10 = fma(C10, C00, C11 * C10), D11 = fma(C10, C01, C11 * C11);
        double T00 = fma(D00, B00, D01 * B10), T01 = fma(D00, B01, D01 * B11);
        double T10 = fma(D10, B00, D11 * B10), T11 = fma(D10, B01, D11 * B11);
        double s1 = 0.0, s2 = 0.0;
        #pragma unroll
        for (int g = 0; g < 8; ++g) {
            Sseg[g][c][0] = s1;
            Sseg[g][c][1] = s2;
            double e1 = Lseg[g][c][0], e2 = Lseg[g][c][1];
            double n1 = fma(T00, s1, fma(T01, s2, e1));
            double n2 = fma(T10, s1, fma(T11, s2, e2));
            s1 = n1; s2 = n2;
        }
    }
    __syncthreads();

    // phase 3: rescan from exact boundary state, emit states for k >= 40
    if (seg >= 4) {
        double s1 = Sseg[seg][c][0], s2 = Sseg[seg][c][1];
        #pragma unroll
        for (int i = 0; i < 10; ++i) {
            int kk = seg * 10 + i - CH0;
            g_S[s][kk][c][0] = s1;
            g_S[s][kk][c][1] = s2;
            double n1 = fma(A00, s1, fma(A01, s2, e[i][0]));
            double n2 = fma(A10, s1, fma(A11, s2, e[i][1]));
            s1 = n1; s2 = n2;
        }
    }
}

// ---------------------------------------------------------------------------
// pass1b: chunks 40..79 with exact init states -> final bf16 Y.
// Task = 64 threads (2 warps), 1 channel/thread, double-float coefficients,
// strength-reduced store pointer (constant +/-128-element stride).
// ---------------------------------------------------------------------------
__global__ void __launch_bounds__(128) pass1b(
    const float* __restrict__ pred, const float* __restrict__ targ)
{
    __shared__ float xs2[2][LCH];
    int tid = threadIdx.x;
    int half = tid >> 6;
    int c    = tid & 63;
    int task = blockIdx.x * 2 + half;        // 0..639
    int kk = task % NCHV;
    int s  = task / NCHV;
    int k  = kk + CH0;
    int sig = s >> 3, b = (s >> 1) & 3, dir = s & 1;
    const float* x = (sig ? targ : pred) + b * TLEN;
    float* xs = xs2[half];

    int k0 = k * LCH;
    if (dir == 0) {
        for (int j = c; j < LCH; j += 64) xs[j] = x[k0 + j];
    } else {
        for (int j = c; j < LCH; j += 64) xs[j] = x[TLEN - 1 - (k0 + j)];
    }
    __syncthreads();

    double a1d = -g_c[0][c], a2d = -g_c[1][c];
    float n1h = (float)a1d, n1l = (float)(a1d - (double)n1h);
    float n2h = (float)a2d, n2l = (float)(a2d - (double)n2h);
    float b0f = (float)g_c[2][c];

    float y1 = (float)g_S[s][kk][c][0], y2 = (float)g_S[s][kk][c][1];

    int tl0 = dir ? (TLEN - 1 - MARGIN - k0) : (k0 - MARGIN);
    __nv_bfloat16* yp = g_Yh + (size_t)((sig * 4 + b) * TV + tl0) * 128
                             + dir * 64 + c;
    const int pstep = dir ? -128 : 128;

    #pragma unroll 8
    for (int j = 0; j < LCH; ++j) {
        float i0 = fmaf(n2l, y2, b0f * xs[j]);
        float t0 = fmaf(n1l, y1, i0);
        float m0 = fmaf(n2h, y2, t0);
        float y  = fmaf(n1h, y1, m0);
        *yp = __float2bfloat16_rn(y);
        yp += pstep;
        y2 = y1; y1 = y;
    }
}

// ---------------------------------------------------------------------------
// Stage B helpers
// ---------------------------------------------------------------------------
__device__ __forceinline__ float tanh_fast(float x) {
    float r;
    asm("tanh.approx.f32 %0, %1;" : "=f"(r) : "f"(x));
    return r;
}
__device__ __forceinline__ void ldsm4(unsigned& r0, unsigned& r1,
                                      unsigned& r2, unsigned& r3,
                                      unsigned addr) {
    asm volatile("ldmatrix.sync.aligned.m8n8.x4.shared.b16 {%0,%1,%2,%3}, [%4];"
                 : "=r"(r0), "=r"(r1), "=r"(r2), "=r"(r3) : "r"(addr));
}
__device__ __forceinline__ void mma16816(float* d, const unsigned* a,
                                         unsigned b0, unsigned b1) {
    asm volatile(
        "mma.sync.aligned.m16n8k16.row.col.f32.bf16.bf16.f32 "
        "{%0,%1,%2,%3}, {%4,%5,%6,%7}, {%8,%9}, {%0,%1,%2,%3};"
        : "+f"(d[0]), "+f"(d[1]), "+f"(d[2]), "+f"(d[3])
        : "r"(a[0]), "r"(a[1]), "r"(a[2]), "r"(a[3]), "r"(b0), "r"(b1));
}
__device__ __forceinline__ void cp16(unsigned dst, const void* src) {
    asm volatile("cp.async.ca.shared.global [%0], [%1], 16;"
                 :: "r"(dst), "l"(src));
}

// ---------------------------------------------------------------------------
// Stage B: staging + GEMM + epilogue (Y is already fully corrected).
// ---------------------------------------------------------------------------
__global__ void __launch_bounds__(128, 4) stageB() {
    extern __shared__ char sm[];
    int tid = threadIdx.x;
    int b   = blockIdx.y;
    int t0  = blockIdx.x * TT;
    unsigned sb = (unsigned)__cvta_generic_to_shared(sm);

    // ---- stage W (prepacked bf16) via cp.async: 1024 uint4 ----
    {
        const uint4* src = (const uint4*)g_Wh;
        #pragma unroll
        for (int it = 0; it < 8; ++it) {
            int i = tid + it * 128;
            int o = i >> 4, q = i & 15;
            cp16(sb + o * ROWB + q * 16, src + i);
        }
    }
    // ---- stage Y tiles via cp.async: 2048 uint4 (32KB) ----
    {
        const uint4* srcP = (const uint4*)(g_Yh + ((size_t)(0 * 4 + b) * TV + t0) * 128);
        const uint4* srcT = (const uint4*)(g_Yh + ((size_t)(1 * 4 + b) * TV + t0) * 128);
        #pragma unroll
        for (int it = 0; it < 16; ++it) {
            int idx = tid + it * 128;
            int R = idx >> 4, col = idx & 15;
            int sig = R >> 6, tt = R & 63;
            const uint4* src = (sig ? srcT : srcP) + tt * 16 + col;
            cp16(sb + WBYTES + sig * VSIGB + tt * ROWB + col * 16, src);
        }
    }
    asm volatile("cp.async.commit_group;" ::: "memory");
    asm volatile("cp.async.wait_group 0;" ::: "memory");
    __syncthreads();

    // ---- tensor-core GEMM ----
    int w = tid >> 5, lane = tid & 31;
    int tw = w * 16;
    unsigned a_base = sb + (unsigned)(lane & 15) * ROWB
                         + ((lane & 16) ? 16u : 0u);
    unsigned b_base = sb + WBYTES
                    + (unsigned)(tw + (lane & 7) + ((lane & 16) ? 8 : 0)) * ROWB
                    + ((lane & 8) ? 16u : 0u);

    float acc[2][4][2][4];
    #pragma unroll
    for (int s2 = 0; s2 < 2; ++s2)
        #pragma unroll
        for (int m = 0; m < 4; ++m)
            #pragma unroll
            for (int n = 0; n < 2; ++n)
                #pragma unroll
                for (int i = 0; i < 4; ++i) acc[s2][m][n][i] = 0.f;

    #pragma unroll
    for (int k = 0; k < 8; ++k) {
        unsigned a[4][4];
        #pragma unroll
        for (int m = 0; m < 4; ++m)
            ldsm4(a[m][0], a[m][1], a[m][2], a[m][3],
                  a_base + (unsigned)m * (16 * ROWB) + (unsigned)k * 32);
        #pragma unroll
        for (int s2 = 0; s2 < 2; ++s2) {
            unsigned r0, r1, r2, r3;
            ldsm4(r0, r1, r2, r3,
                  b_base + (unsigned)s2 * VSIGB + (unsigned)k * 32);
            #pragma unroll
            for (int m = 0; m < 4; ++m) {
                mma16816(acc[s2][m][0], a[m], r0, r1);
                mma16816(acc[s2][m][1], a[m], r2, r3);
            }
        }
    }

    // ---- epilogue: |tanh(p) - tanh(t)| ----
    float lsum = 0.f;
    #pragma unroll
    for (int m = 0; m < 4; ++m)
        #pragma unroll
        for (int n = 0; n < 2; ++n)
            #pragma unroll
            for (int i = 0; i < 4; ++i)
                lsum += fabsf(tanh_fast(acc[0][m][n][i])
                            - tanh_fast(acc[1][m][n][i]));

    #pragma unroll
    for (int off = 16; off; off >>= 1)
        lsum += __shfl_xor_sync(0xffffffffu, lsum, off);

    __shared__ float red[4];
    if (lane == 0) red[w] = lsum;
    __syncthreads();
    if (tid == 0)
        g_part[b * NTB + blockIdx.x] =
            (double)((red[0] + red[1]) + (red[2] + red[3]));
}

// ---------------------------------------------------------------------------
// Deterministic final reduction -> mean
// ---------------------------------------------------------------------------
__global__ void __launch_bounds__(256) finalize(float* out) {
    __shared__ double sd[256];
    double acc = 0.0;
    for (int i = threadIdx.x; i < NPART; i += 256) acc += g_part[i];
    sd[threadIdx.x] = acc;
    __syncthreads();
    for (int s = 128; s > 0; s >>= 1) {
        if (threadIdx.x < s) sd[threadIdx.x] += sd[threadIdx.x + s];
        __syncthreads();
    }
    if (threadIdx.x == 0)
        out[0] = (float)(sd[0] / (4.0 * 64.0 * 40000.0));
}

// ---------------------------------------------------------------------------
extern "C" void kernel_launch(void* const* d_in, const int* in_sizes, int n_in,
                              void* d_out, int out_size) {
    const float *pred = 0, *targ = 0, *W = 0;
    const void  *cf[3] = { 0, 0, 0 };
    int nBig = 0, nSmall = 0;
    for (int i = 0; i < n_in; ++i) {
        int sz = in_sizes[i];
        if (sz == 480000) {
            if (nBig == 0) pred = (const float*)d_in[i];
            else           targ = (const float*)d_in[i];
            ++nBig;
        } else if (sz == 64 && nSmall < 3) {
            cf[nSmall++] = d_in[i];
        } else if (sz == 8192) {
            W = (const float*)d_in[i];
        }
    }
    float* out = (float*)d_out;

    cudaFuncSetAttribute(stageB, cudaFuncAttributeMaxDynamicSharedMemorySize,
                         SMEM_B);

    prep<<<1, 64>>>(cf[0], cf[1], cf[2], W);
    pass1a<<<(NCHUNK * NSEQ) / 2, 128>>>(pred, targ);
    combine<<<NSEQ, 512>>>();
    pass1b<<<(NCHV * NSEQ) / 2, 128>>>(pred, targ);
    stageB<<<dim3(NTB, 4), 128, SMEM_B>>>();
    finalize<<<1, 256>>>(out);
}

// round 17
// speedup vs baseline: 1.7356x; 1.0181x over previous
#include <cuda_runtime.h>
#include <cuda_bf16.h>
#include <math.h>

// ---------------------------------------------------------------------------
// ESpaceLoss: biquad filter bank fwd+bwd -> tanh(W x) -> mean |p - t|
//
//   prep    : value-classified, dtype-robust coefficient load + analytic
//             fp64 reconstruction; W -> bf16; A500 = M^500, A = A500^2.
//   pass1a  : per (seq,chunk) zero-init fp32 recurrence, 1 channel/thread,
//             end states -> g_E, mid-chunk snapshot -> g_Emid.
//   combine : hierarchical scan (8 seg x 10 chunks, A^10 jumps) -> exact
//             fp64 init states g_S (chunk start) and g_Sm (chunk middle).
//   pass1b  : 500-step half-chunk tasks seeded with exact states (plain
//             fp32 coefficients); writes final bf16 Y.
//   stageB  : cp.async staging + bf16 mma.sync GEMM + tanh.approx |diff|.
//   finalize: deterministic reduction -> scalar mean
// ---------------------------------------------------------------------------

#define TLEN   120000
#define LCH    1000
#define HLCH   500
#define NCHUNK 80
#define CH0    40
#define NCHV   40
#define MARGIN 40000
#define TV     40000
#define NC     64
#define NSEQ   16
#define TT     64          // stage B t-tile
#define NTB    (TV / TT)   // 625
#define NPART  (NTB * 4)   // 2500

#define ROWB   272                     // bf16 tile row stride in bytes (17 lines)
#define WBYTES (64 * ROWB)             // 17408
#define VSIGB  (64 * ROWB)             // 17408 per signal
#define SMEM_B (WBYTES + 2 * VSIGB)    // 52224

__device__ double g_c[3][NC];                  // a1, a2, b0 (normalized fp64)
__device__ double g_A[NC][4];                  // M^1000
__device__ double g_A5[NC][4];                 // M^500
__device__ double g_E[NSEQ][NCHUNK][NC][2];    // particular end states
__device__ double g_Emid[NSEQ][NCHUNK][NC][2]; // particular mid states (k>=CH0)
__device__ double g_S[NSEQ][NCHV][NC][2];      // exact init state at chunk start
__device__ double g_Sm[NSEQ][NCHV][NC][2];     // exact state at chunk middle
__device__ unsigned g_Wh[4096];                // W as bf16x2, [o][c-pair]
__device__ __nv_bfloat16 g_Yh[(size_t)2 * 4 * TV * 128]; // [sig][b][t][dir*64+c]
__device__ double g_part[NPART];

// ---------------------------------------------------------------------------
// Coefficient prep + W pack + A500 / A1000.
// ---------------------------------------------------------------------------
__device__ __forceinline__ int coeff_class(double v) {
    if (!isfinite(v)) return -1;
    if (v > -2.5 && v < -1.5) return 0;       // a1
    if (v >  0.5 && v <  1.5) return 1;       // a2
    if (v > 1e-7 && v < 1e-2) return 2;       // b0
    return -1;
}

__global__ void __launch_bounds__(64) prep(const void* p0, const void* p1,
                                           const void* p2,
                                           const float* __restrict__ W) {
    const void* bufs[3] = { p0, p1, p2 };
    int c = threadIdx.x;
    __shared__ int slot[3];
    __shared__ int use64;
    __shared__ int mism;

    if (c == 0) {
        int cf[3], cd[3];
        for (int k = 0; k < 3; ++k) {
            cf[k] = coeff_class((double)((const float*)bufs[k])[0]);
            cd[k] = coeff_class(((const double*)bufs[k])[0]);
        }
        bool okf = cf[0] >= 0 && cf[1] >= 0 && cf[2] >= 0 &&
                   cf[0] != cf[1] && cf[0] != cf[2] && cf[1] != cf[2];
        bool okd = cd[0] >= 0 && cd[1] >= 0 && cd[2] >= 0 &&
                   cd[0] != cd[1] && cd[0] != cd[2] && cd[1] != cd[2];
        use64 = okf ? 0 : 1;
        for (int k = 0; k < 3; ++k)
            slot[k] = okf ? cf[k] : (okd ? cd[k] : k);
        mism = 0;
    }
    __syncthreads();

    for (int k = 0; k < 3; ++k) {
        double v = use64 ? ((const double*)bufs[k])[c]
                         : (double)((const float*)bufs[k])[c];
        g_c[slot[k]][c] = v;
    }
    __syncthreads();

    const double PI = 3.14159265358979323846;
    double lmin = log(2.0 * PI * 10.0  / 24000.0);
    double lmax = log(2.0 * PI * 100.0 / 24000.0);
    double th = exp(lmin + (double)c * ((lmax - lmin) / 63.0));
    double r  = 0.9999 + (double)c * ((0.99999 - 0.9999) / 63.0);
    if (c == 63) { th = 2.0 * PI * 100.0 / 24000.0; r = 0.99999; }
    double ra1 = -2.0 * r * cos(th);
    double ra2 = r * r;
    double rb0 = (1.0 - r) * 0.5;

    if (fabs(ra1 - g_c[0][c]) > 1e-5 ||
        fabs(ra2 - g_c[1][c]) > 1e-5 ||
        fabs(rb0 - g_c[2][c]) > 1e-8)
        atomicOr(&mism, 1);
    __syncthreads();

    if (!mism) {
        g_c[0][c] = ra1;
        g_c[1][c] = ra2;
        g_c[2][c] = rb0;
    }
    __syncthreads();

    // A500 = M^500 by binary powering; A1000 = A500^2.
    {
        double m00 = -g_c[0][c], m01 = -g_c[1][c];
        double p00 = 1, p01 = 0, p10 = 0, p11 = 1;
        double b00 = m00, b01 = m01, b10 = 1.0, b11 = 0.0;
        int e = HLCH;
        while (e) {
            if (e & 1) {
                double t00 = p00 * b00 + p01 * b10, t01 = p00 * b01 + p01 * b11;
                double t10 = p10 * b00 + p11 * b10, t11 = p10 * b01 + p11 * b11;
                p00 = t00; p01 = t01; p10 = t10; p11 = t11;
            }
            e >>= 1;
            if (e) {
                double t00 = b00 * b00 + b01 * b10, t01 = b00 * b01 + b01 * b11;
                double t10 = b10 * b00 + b11 * b10, t11 = b10 * b01 + b11 * b11;
                b00 = t00; b01 = t01; b10 = t10; b11 = t11;
            }
        }
        g_A5[c][0] = p00; g_A5[c][1] = p01;
        g_A5[c][2] = p10; g_A5[c][3] = p11;
        g_A[c][0] = fma(p00, p00, p01 * p10);
        g_A[c][1] = fma(p00, p01, p01 * p11);
        g_A[c][2] = fma(p10, p00, p11 * p10);
        g_A[c][3] = fma(p10, p01, p11 * p11);
    }

    // pack W -> bf16x2
    const float2* Wf2 = (const float2*)W;
    for (int i = c; i < 4096; i += 64) {
        float2 wv = Wf2[i];
        unsigned u;
        asm("cvt.rn.bf16x2.f32 %0, %1, %2;" : "=r"(u) : "f"(wv.y), "f"(wv.x));
        g_Wh[i] = u;
    }
}

// ---------------------------------------------------------------------------
// pass1a: zero-init recurrence, end + mid states. Task = 64 threads,
// 1 channel/thread, plain fp32 coefficients. Block = 128 thr = 2 tasks.
// ---------------------------------------------------------------------------
__global__ void __launch_bounds__(128) pass1a(
    const float* __restrict__ pred, const float* __restrict__ targ)
{
    __shared__ float xs2[2][LCH];
    int tid = threadIdx.x;
    int half = tid >> 6;
    int c    = tid & 63;
    int task = blockIdx.x * 2 + half;        // 0..1279
    int k = task % NCHUNK;
    int s = task / NCHUNK;
    int sig = s >> 3, b = (s >> 1) & 3, dir = s & 1;
    const float* x = (sig ? targ : pred) + b * TLEN;
    float* xs = xs2[half];

    int k0 = k * LCH;
    if (dir == 0) {
        for (int j = c; j < LCH; j += 64) xs[j] = x[k0 + j];
    } else {
        for (int j = c; j < LCH; j += 64) xs[j] = x[TLEN - 1 - (k0 + j)];
    }
    __syncthreads();

    float n1 = (float)(-g_c[0][c]), n2 = (float)(-g_c[1][c]);
    float b0 = (float)g_c[2][c];

    float y1 = 0.f, y2 = 0.f;
    #pragma unroll 4
    for (int j = 0; j < HLCH; ++j) {
        float y = fmaf(n1, y1, fmaf(n2, y2, b0 * xs[j]));
        y2 = y1; y1 = y;
    }
    if (k >= CH0) {
        g_Emid[s][k][c][0] = (double)y1;
        g_Emid[s][k][c][1] = (double)y2;
    }
    #pragma unroll 4
    for (int j = HLCH; j < LCH; ++j) {
        float y = fmaf(n1, y1, fmaf(n2, y2, b0 * xs[j]));
        y2 = y1; y1 = y;
    }
    g_E[s][k][c][0] = (double)y1;
    g_E[s][k][c][1] = (double)y2;
}

// ---------------------------------------------------------------------------
// combine: hierarchical scan; phase 3 also emits exact mid-chunk states
// (s_mid = A500 * s + e_mid).
// ---------------------------------------------------------------------------
__global__ void __launch_bounds__(512) combine() {
    __shared__ double Lseg[8][NC][2];
    __shared__ double Sseg[8][NC][2];
    int s   = blockIdx.x;
    int c   = threadIdx.x & 63;
    int seg = threadIdx.x >> 6;

    double A00 = g_A[c][0], A01 = g_A[c][1], A10 = g_A[c][2], A11 = g_A[c][3];

    double e[10][2];
    #pragma unroll
    for (int i = 0; i < 10; ++i) {
        e[i][0] = g_E[s][seg * 10 + i][c][0];
        e[i][1] = g_E[s][seg * 10 + i][c][1];
    }

    double l1 = 0.0, l2 = 0.0;
    #pragma unroll
    for (int i = 0; i < 10; ++i) {
        double n1 = fma(A00, l1, fma(A01, l2, e[i][0]));
        double n2 = fma(A10, l1, fma(A11, l2, e[i][1]));
        l1 = n1; l2 = n2;
    }
    Lseg[seg][c][0] = l1;
    Lseg[seg][c][1] = l2;
    __syncthreads();

    if (seg == 0) {
        double B00 = fma(A00, A00, A01 * A10), B01 = fma(A00, A01, A01 * A11);
        double B10 = fma(A10, A00, A11 * A10), B11 = fma(A10, A01, A11 * A11);
        double C00 = fma(B00, B00, B01 * B10), C01 = fma(B00, B01, B01 * B11);
        double C10 = fma(B10, B00, B11 * B10), C11 = fma(B10, B01, B11 * B11);
        double D00 = fma(C00, C00, C01 * C10), D01 = fma(C00, C01, C01 * C11);
        double D10 = fma(C10, C00, C11 * C10), D11 = fma(C10, C01, C11 * C11);
        double T00 = fma(D00, B00, D01 * B10), T01 = fma(D00, B01, D01 * B11);
        double T10 = fma(D10, B00, D11 * B10), T11 = fma(D10, B01, D11 * B11);
        double s1 = 0.0, s2 = 0.0;
        #pragma unroll
        for (int g = 0; g < 8; ++g) {
            Sseg[g][c][0] = s1;
            Sseg[g][c][1] = s2;
            double e1 = Lseg[g][c][0], e2 = Lseg[g][c][1];
            double n1 = fma(T00, s1, fma(T01, s2, e1));
            double n2 = fma(T10, s1, fma(T11, s2, e2));
            s1 = n1; s2 = n2;
        }
    }
    __syncthreads();

    if (seg >= 4) {
        double F00 = g_A5[c][0], F01 = g_A5[c][1];
        double F10 = g_A5[c][2], F11 = g_A5[c][3];
        double s1 = Sseg[seg][c][0], s2 = Sseg[seg][c][1];
        #pragma unroll
        for (int i = 0; i < 10; ++i) {
            int k = seg * 10 + i;
            int kk = k - CH0;
            g_S[s][kk][c][0] = s1;
            g_S[s][kk][c][1] = s2;
            double m1 = g_Emid[s][k][c][0], m2 = g_Emid[s][k][c][1];
            g_Sm[s][kk][c][0] = fma(F00, s1, fma(F01, s2, m1));
            g_Sm[s][kk][c][1] = fma(F10, s1, fma(F11, s2, m2));
            double n1 = fma(A00, s1, fma(A01, s2, e[i][0]));
            double n2 = fma(A10, s1, fma(A11, s2, e[i][1]));
            s1 = n1; s2 = n2;
        }
    }
}

// ---------------------------------------------------------------------------
// pass1b: 500-step half-chunk tasks with exact init states -> final bf16 Y.
// Plain fp32 coefficients (8-cyc chain), 1 channel/thread.
// ---------------------------------------------------------------------------
__global__ void __launch_bounds__(128) pass1b(
    const float* __restrict__ pred, const float* __restrict__ targ)
{
    __shared__ float xs2[2][HLCH];
    int tid = threadIdx.x;
    int bh = tid >> 6;
    int c  = tid & 63;
    int task = blockIdx.x * 2 + bh;          // 0..1279
    int hc = task % (NCHV * 2);              // half-chunk 0..79
    int s  = task / (NCHV * 2);
    int kk = hc >> 1, h = hc & 1;
    int k  = kk + CH0;
    int sig = s >> 3, b = (s >> 1) & 3, dir = s & 1;
    const float* x = (sig ? targ : pred) + b * TLEN;
    float* xs = xs2[bh];

    int k0 = k * LCH + h * HLCH;
    if (dir == 0) {
        for (int j = c; j < HLCH; j += 64) xs[j] = x[k0 + j];
    } else {
        for (int j = c; j < HLCH; j += 64) xs[j] = x[TLEN - 1 - (k0 + j)];
    }
    __syncthreads();

    float n1 = (float)(-g_c[0][c]), n2 = (float)(-g_c[1][c]);
    float b0 = (float)g_c[2][c];

    const double* Ssrc = h ? &g_Sm[s][kk][c][0] : &g_S[s][kk][c][0];
    float y1 = (float)Ssrc[0], y2 = (float)Ssrc[1];

    int tl0 = dir ? (TLEN - 1 - MARGIN - k0) : (k0 - MARGIN);
    __nv_bfloat16* yp = g_Yh + (size_t)((sig * 4 + b) * TV + tl0) * 128
                             + dir * 64 + c;
    const int pstep = dir ? -128 : 128;

    #pragma unroll 4
    for (int j = 0; j < HLCH; ++j) {
        float y = fmaf(n1, y1, fmaf(n2, y2, b0 * xs[j]));
        *yp = __float2bfloat16_rn(y);
        yp += pstep;
        y2 = y1; y1 = y;
    }
}

// ---------------------------------------------------------------------------
// Stage B helpers
// ---------------------------------------------------------------------------
__device__ __forceinline__ float tanh_fast(float x) {
    float r;
    asm("tanh.approx.f32 %0, %1;" : "=f"(r) : "f"(x));
    return r;
}
__device__ __forceinline__ void ldsm4(unsigned& r0, unsigned& r1,
                                      unsigned& r2, unsigned& r3,
                                      unsigned addr) {
    asm volatile("ldmatrix.sync.aligned.m8n8.x4.shared.b16 {%0,%1,%2,%3}, [%4];"
                 : "=r"(r0), "=r"(r1), "=r"(r2), "=r"(r3) : "r"(addr));
}
__device__ __forceinline__ void mma16816(float* d, const unsigned* a,
                                         unsigned b0, unsigned b1) {
    asm volatile(
        "mma.sync.aligned.m16n8k16.row.col.f32.bf16.bf16.f32 "
        "{%0,%1,%2,%3}, {%4,%5,%6,%7}, {%8,%9}, {%0,%1,%2,%3};"
        : "+f"(d[0]), "+f"(d[1]), "+f"(d[2]), "+f"(d[3])
        : "r"(a[0]), "r"(a[1]), "r"(a[2]), "r"(a[3]), "r"(b0), "r"(b1));
}
__device__ __forceinline__ void cp16(unsigned dst, const void* src) {
    asm volatile("cp.async.ca.shared.global [%0], [%1], 16;"
                 :: "r"(dst), "l"(src));
}

// ---------------------------------------------------------------------------
// Stage B: staging + GEMM + epilogue.
// ---------------------------------------------------------------------------
__global__ void __launch_bounds__(128, 4) stageB() {
    extern __shared__ char sm[];
    int tid = threadIdx.x;
    int b   = blockIdx.y;
    int t0  = blockIdx.x * TT;
    unsigned sb = (unsigned)__cvta_generic_to_shared(sm);

    {
        const uint4* src = (const uint4*)g_Wh;
        #pragma unroll
        for (int it = 0; it < 8; ++it) {
            int i = tid + it * 128;
            int o = i >> 4, q = i & 15;
            cp16(sb + o * ROWB + q * 16, src + i);
        }
    }
    {
        const uint4* srcP = (const uint4*)(g_Yh + ((size_t)(0 * 4 + b) * TV + t0) * 128);
        const uint4* srcT = (const uint4*)(g_Yh + ((size_t)(1 * 4 + b) * TV + t0) * 128);
        #pragma unroll
        for (int it = 0; it < 16; ++it) {
            int idx = tid + it * 128;
            int R = idx >> 4, col = idx & 15;
            int sig = R >> 6, tt = R & 63;
            const uint4* src = (sig ? srcT : srcP) + tt * 16 + col;
            cp16(sb + WBYTES + sig * VSIGB + tt * ROWB + col * 16, src);
        }
    }
    asm volatile("cp.async.commit_group;" ::: "memory");
    asm volatile("cp.async.wait_group 0;" ::: "memory");
    __syncthreads();

    int w = tid >> 5, lane = tid & 31;
    int tw = w * 16;
    unsigned a_base = sb + (unsigned)(lane & 15) * ROWB
                         + ((lane & 16) ? 16u : 0u);
    unsigned b_base = sb + WBYTES
                    + (unsigned)(tw + (lane & 7) + ((lane & 16) ? 8 : 0)) * ROWB
                    + ((lane & 8) ? 16u : 0u);

    float acc[2][4][2][4];
    #pragma unroll
    for (int s2 = 0; s2 < 2; ++s2)
        #pragma unroll
        for (int m = 0; m < 4; ++m)
            #pragma unroll
            for (int n = 0; n < 2; ++n)
                #pragma unroll
                for (int i = 0; i < 4; ++i) acc[s2][m][n][i] = 0.f;

    #pragma unroll
    for (int k = 0; k < 8; ++k) {
        unsigned a[4][4];
        #pragma unroll
        for (int m = 0; m < 4; ++m)
            ldsm4(a[m][0], a[m][1], a[m][2], a[m][3],
                  a_base + (unsigned)m * (16 * ROWB) + (unsigned)k * 32);
        #pragma unroll
        for (int s2 = 0; s2 < 2; ++s2) {
            unsigned r0, r1, r2, r3;
            ldsm4(r0, r1, r2, r3,
                  b_base + (unsigned)s2 * VSIGB + (unsigned)k * 32);
            #pragma unroll
            for (int m = 0; m < 4; ++m) {
                mma16816(acc[s2][m][0], a[m], r0, r1);
                mma16816(acc[s2][m][1], a[m], r2, r3);
            }
        }
    }

    float lsum = 0.f;
    #pragma unroll
    for (int m = 0; m < 4; ++m)
        #pragma unroll
        for (int n = 0; n < 2; ++n)
            #pragma unroll
            for (int i = 0; i < 4; ++i)
                lsum += fabsf(tanh_fast(acc[0][m][n][i])
                            - tanh_fast(acc[1][m][n][i]));

    #pragma unroll
    for (int off = 16; off; off >>= 1)
        lsum += __shfl_xor_sync(0xffffffffu, lsum, off);

    __shared__ float red[4];
    if (lane == 0) red[w] = lsum;
    __syncthreads();
    if (tid == 0)
        g_part[b * NTB + blockIdx.x] =
            (double)((red[0] + red[1]) + (red[2] + red[3]));
}

// ---------------------------------------------------------------------------
// Deterministic final reduction -> mean
// ---------------------------------------------------------------------------
__global__ void __launch_bounds__(256) finalize(float* out) {
    __shared__ double sd[256];
    double acc = 0.0;
    for (int i = threadIdx.x; i < NPART; i += 256) acc += g_part[i];
    sd[threadIdx.x] = acc;
    __syncthreads();
    for (int s = 128; s > 0; s >>= 1) {
        if (threadIdx.x < s) sd[threadIdx.x] += sd[threadIdx.x + s];
        __syncthreads();
    }
    if (threadIdx.x == 0)
        out[0] = (float)(sd[0] / (4.0 * 64.0 * 40000.0));
}

// ---------------------------------------------------------------------------
extern "C" void kernel_launch(void* const* d_in, const int* in_sizes, int n_in,
                              void* d_out, int out_size) {
    const float *pred = 0, *targ = 0, *W = 0;
    const void  *cf[3] = { 0, 0, 0 };
    int nBig = 0, nSmall = 0;
    for (int i = 0; i < n_in; ++i) {
        int sz = in_sizes[i];
        if (sz == 480000) {
            if (nBig == 0) pred = (const float*)d_in[i];
            else           targ = (const float*)d_in[i];
            ++nBig;
        } else if (sz == 64 && nSmall < 3) {
            cf[nSmall++] = d_in[i];
        } else if (sz == 8192) {
            W = (const float*)d_in[i];
        }
    }
    float* out = (float*)d_out;

    cudaFuncSetAttribute(stageB, cudaFuncAttributeMaxDynamicSharedMemorySize,
                         SMEM_B);

    prep<<<1, 64>>>(cf[0], cf[1], cf[2], W);
    pass1a<<<(NCHUNK * NSEQ) / 2, 128>>>(pred, targ);
    combine<<<NSEQ, 512>>>();
    pass1b<<<NSEQ * NCHV, 128>>>(pred, targ);
    stageB<<<dim3(NTB, 4), 128, SMEM_B>>>();
    finalize<<<1, 256>>>(out);
}